// round 13
// baseline (speedup 1.0000x reference)
#include <cuda_runtime.h>
#include <cstdint>

// ---------------- problem constants ----------------
#define HH 352
#define WW 1216
#define BB 2
#define PP 65536
#define CC 64
#define KSLOTS 8
#define HXR 2   // splat half-extent x: ceil(1.5/1216*2 * 1216/2) = ceil(1.5)
#define HYR 1   // splat half-extent y: ceil(1.5/1216*2 * 352/2)  = ceil(0.434)

static constexpr int    NPIX   = BB * HH * WW;          // 856064
static constexpr int    HWPIX  = HH * WW;               // 428032
static constexpr double R_D    = 1.5 / 1216.0 * 2.0;    // NDC radius
static __device__ __constant__ float R2F = (float)(R_D * R_D);  // r^2 == r^RAD_POW

static constexpr unsigned long long SENT = 0xFFFFFFFFFFFFFFFFULL;

// ---------------- scratch (no allocations allowed) ----------------
__device__ unsigned long long g_slots[(size_t)NPIX * KSLOTS];   // ~54.8 MB
__device__ float              g_feats[(size_t)BB * PP * CC];    // ~33.5 MB

// ---------------- kernels ----------------

// src [B,C,P] -> g_feats [B*P, C]  (smem-tiled, both sides coalesced)
__global__ void __launch_bounds__(256) transpose_kernel(const float* __restrict__ src) {
    __shared__ float tile[32][33];
    int b  = blockIdx.z;
    int p0 = blockIdx.x * 32;
    int c0 = blockIdx.y * 32;
    #pragma unroll
    for (int i = threadIdx.y; i < 32; i += 8)
        tile[i][threadIdx.x] = __ldg(&src[((size_t)b * CC + (c0 + i)) * PP + p0 + threadIdx.x]);
    __syncthreads();
    #pragma unroll
    for (int i = threadIdx.y; i < 32; i += 8)
        g_feats[((size_t)b * PP + (p0 + i)) * CC + c0 + threadIdx.x] = tile[threadIdx.x][i];
}

// One thread per packed point; atomicMin cascade maintains the K smallest keys
// per pixel. Key = (float-bits(z) << 32) | pid. z > 0 so float-bit order ==
// numeric order; low pid bits reproduce the reference lexsort's stable z-tie
// break (per pixel each point contributes <=1 candidate, flat order pid-major).
// Invariants: (a) multiset {slots} U {in-flight carries} preserved; (b) carries
// are non-decreasing along the walk => slots end sorted ascending with the
// sentinels as a suffix; (c) every slot value is monotonically non-increasing
// over time (atomicMin-only writes). (c) licenses the slot[7] pre-check: any
// read (even stale, since stale >= current) that is <= key proves key can
// never be among the final 8 smallest. __ldcg reads the L2 copy the atomics
// mutate, maximizing reject freshness; an L1-stale plain load would still be
// correct but would reject almost nothing.
__global__ void __launch_bounds__(256) scatter_kernel(const float* __restrict__ pts) {
    int t = blockIdx.x * blockDim.x + threadIdx.x;   // packed pid = b*P + p
    if (t >= BB * PP) return;
    float x = __ldg(&pts[t * 3 + 0]);
    float y = __ldg(&pts[t * 3 + 1]);
    float z = __ldg(&pts[t * 3 + 2]);
    if (!(z > 0.0f)) return;
    int b  = t >> 16;                                 // t / P  (P = 65536)
    int i0 = (int)floorf((y + 1.0f) * 0.5f * (float)HH);
    int j0 = (int)floorf((x + 1.0f) * 0.5f * (float)WW);
    unsigned long long zkey = ((unsigned long long)__float_as_uint(z) << 32);

    #pragma unroll
    for (int dy = -HYR; dy <= HYR; ++dy) {
        int ii = i0 + dy;
        if (ii < 0 || ii >= HH) continue;
        float yc  = ((float)ii + 0.5f) * (2.0f / (float)HH) - 1.0f;
        float dyv = y - yc;
        float dy2 = dyv * dyv;
        #pragma unroll
        for (int dx = -HXR; dx <= HXR; ++dx) {
            int jj = j0 + dx;
            if (jj < 0 || jj >= WW) continue;
            float xc  = ((float)jj + 0.5f) * (2.0f / (float)WW) - 1.0f;
            float dxv = x - xc;
            float d2  = dxv * dxv + dy2;
            if (!(d2 < R2F)) continue;
            size_t base = (size_t)((b * HH + ii) * WW + jj) * KSLOTS;
            unsigned long long key = zkey | (unsigned int)t;
            // safe early reject (see invariant (c) above)
            if (__ldcg(&g_slots[base + KSLOTS - 1]) <= key) continue;
            #pragma unroll
            for (int k = 0; k < KSLOTS; ++k) {
                unsigned long long prev = atomicMin(&g_slots[base + k], key);
                if (prev == SENT) break;       // landed in empty slot
                key = max(key, prev);          // displaced value cascades on
            }
        }
    }
}

// block: 32 pixels x 16 channel-groups (4 ch each) = 512 threads
__global__ void __launch_bounds__(512) gather_kernel(const float* __restrict__ pts,
                                                     float* __restrict__ out) {
    __shared__ float w_s[32][KSLOTS];
    __shared__ int   pid_s[32][KSLOTS];

    int pixBase = blockIdx.x * 32;
    int tid = threadIdx.x;

    // cooperative decode of 32*8 = 256 slots
    if (tid < 256) {
        int px = tid >> 3, k = tid & 7;
        int pix = pixBase + px;
        float wv = 0.0f;
        int   pid = -1;
        unsigned long long key = __ldg(&g_slots[(size_t)pix * KSLOTS + k]);
        if (key != SENT) {
            pid = (int)(unsigned int)(key & 0xFFFFFFFFu);
            float x = __ldg(&pts[pid * 3 + 0]);
            float y = __ldg(&pts[pid * 3 + 1]);
            int ij = pix % HWPIX;
            int i = ij / WW, j = ij % WW;
            float xc = ((float)j + 0.5f) * (2.0f / (float)WW) - 1.0f;
            float yc = ((float)i + 0.5f) * (2.0f / (float)HH) - 1.0f;
            float dxv = x - xc, dyv = y - yc;
            float d2 = dxv * dxv + dyv * dyv;
            float dist = d2 / R2F;               // RAD_POW == 2 -> divide by r^2
            dist = fminf(fmaxf(dist, 0.001f), 1.0f);
            wv = 1.0f - sqrtf(dist);             // TAU == 1
        }
        w_s[px][k]  = wv;
        pid_s[px][k] = pid;
    }
    __syncthreads();

    int px  = tid & 31;          // warp spans 32 consecutive pixels, fixed channel group
    int cg  = tid >> 5;          // 0..15
    int pix = pixBase + px;

    float4 acc = make_float4(0.f, 0.f, 0.f, 0.f);
    #pragma unroll
    for (int k = 0; k < KSLOTS; ++k) {
        int pid = pid_s[px][k];
        if (pid < 0) break;      // sentinel suffix => valid entries are contiguous
        float wv = w_s[px][k];
        const float4 f = *reinterpret_cast<const float4*>(&g_feats[(size_t)pid * CC + cg * 4]);
        acc.x += wv * f.x;
        acc.y += wv * f.y;
        acc.z += wv * f.z;
        acc.w += wv * f.w;
    }

    int b  = pix / HWPIX;
    int ij = pix - b * HWPIX;
    float* o = out + ((size_t)b * CC + cg * 4) * HWPIX + ij;
    o[0 * HWPIX] = acc.x;
    o[1 * HWPIX] = acc.y;
    o[2 * HWPIX] = acc.z;
    o[3 * HWPIX] = acc.w;
}

// ---------------- launch ----------------
extern "C" void kernel_launch(void* const* d_in, const int* in_sizes, int n_in,
                              void* d_out, int out_size) {
    const float* pts = (const float*)d_in[0];   // [B,P,3]
    const float* src = (const float*)d_in[1];   // [B,C,P]
    float* out = (float*)d_out;                 // [B,C,H,W]
    (void)in_sizes; (void)n_in; (void)out_size;

    // 1) reset slots: byte-memset 0xFF == SENT. Memset nodes are graph-capturable;
    //    cudaGetSymbolAddress is a pure query (no allocation).
    void* slots_ptr = nullptr;
    cudaGetSymbolAddress(&slots_ptr, g_slots);
    cudaMemsetAsync(slots_ptr, 0xFF, (size_t)NPIX * KSLOTS * sizeof(unsigned long long), 0);

    // 2) transpose features for coalesced gathers (~9 us predicted)
    dim3 tb(32, 8);
    dim3 tg(PP / 32, CC / 32, BB);
    transpose_kernel<<<tg, tb>>>(src);

    // 3) scatter points into per-pixel top-K z-buffers (~12-15 us predicted)
    scatter_kernel<<<(BB * PP + 255) / 256, 256>>>(pts);

    // 4) gather + composite (~40 us predicted, output-write-bound)
    gather_kernel<<<NPIX / 32, 512>>>(pts, out);
}

// round 17
// speedup vs baseline: 1.0730x; 1.0730x over previous
#include <cuda_runtime.h>
#include <cstdint>

// ---------------- problem constants ----------------
#define HH 352
#define WW 1216
#define BB 2
#define PP 65536
#define CC 64
#define KSLOTS 8
#define HXR 2   // splat half-extent x: ceil(1.5)
#define HYR 1   // splat half-extent y: ceil(0.434)

static constexpr int    NPIX   = BB * HH * WW;          // 856064
static constexpr int    HWPIX  = HH * WW;               // 428032
static constexpr double R_D    = 1.5 / 1216.0 * 2.0;    // NDC radius
static __device__ __constant__ float R2F = (float)(R_D * R_D);  // r^2 == r^RAD_POW

static constexpr unsigned int SENT32 = 0xFFFFFFFFu;
static constexpr unsigned int PIDMASK = 0x1FFFFu;       // 17 bits: B*P = 2^17

// ---------------- scratch (no allocations allowed) ----------------
// u32 key = (float_bits(z) & 0xFFFE0000) | pid.
// z > 0 => fbits < 0x80000000 => key < 0x80000000 < SENT32 (never collides).
// 15 z-bits: monotone truncation preserves order; truncation ties break by pid.
// Compositing is an order-independent weighted sum, so ordering only affects
// set membership at the rank-8 boundary; membership flips need a truncation
// tie exactly at that boundary of a >8-candidate pixel (~1e-6 of pixels).
__device__ unsigned int g_slots[(size_t)NPIX * KSLOTS];   // ~27.4 MB
__device__ float        g_feats[(size_t)BB * PP * CC];    // ~33.5 MB

// ---------------- kernels ----------------

// src [B,C,P] -> g_feats [B*P, C].  64p x 32c tile, 8 independent LDGs per
// thread before the single BAR (MLP=8), conflict-free smem both phases.
__global__ void __launch_bounds__(256) transpose_kernel(const float* __restrict__ src) {
    __shared__ float tile[32][65];   // [c][p]: 32 c-rows x 64 p-cols (+1 pad)
    int b  = blockIdx.z;
    int p0 = blockIdx.x * 64;
    int c0 = blockIdx.y * 32;
    int tx = threadIdx.x;            // 0..31
    int ty = threadIdx.y;            // 0..7
    #pragma unroll
    for (int i = ty; i < 32; i += 8) {
        const float* row = &src[((size_t)b * CC + (c0 + i)) * PP + p0];
        tile[i][tx]      = __ldg(&row[tx]);
        tile[i][tx + 32] = __ldg(&row[tx + 32]);
    }
    __syncthreads();
    #pragma unroll
    for (int i = ty; i < 64; i += 8)
        g_feats[((size_t)b * PP + (p0 + i)) * CC + c0 + tx] = tile[tx][i];
}

// One thread per packed point; atomicMin cascade maintains the K smallest u32
// keys per pixel. Invariants: (a) multiset {slots} U {carries} preserved;
// (b) carries non-decreasing => slots end sorted ascending, sentinel suffix;
// (c) slot values monotonically non-increasing => slot[7] pre-check is safe
// (stale >= current, so stale <= key proves key can never place). __ldcg reads
// the L2 copy the atomics mutate for maximal reject freshness.
__global__ void __launch_bounds__(256) scatter_kernel(const float* __restrict__ pts) {
    int t = blockIdx.x * blockDim.x + threadIdx.x;   // packed pid = b*P + p
    if (t >= BB * PP) return;
    float x = __ldg(&pts[t * 3 + 0]);
    float y = __ldg(&pts[t * 3 + 1]);
    float z = __ldg(&pts[t * 3 + 2]);
    if (!(z > 0.0f)) return;
    int b  = t >> 16;                                 // t / P  (P = 65536)
    int i0 = (int)floorf((y + 1.0f) * 0.5f * (float)HH);
    int j0 = (int)floorf((x + 1.0f) * 0.5f * (float)WW);
    unsigned int zbits = __float_as_uint(z) & 0xFFFE0000u;

    #pragma unroll
    for (int dy = -HYR; dy <= HYR; ++dy) {
        int ii = i0 + dy;
        if (ii < 0 || ii >= HH) continue;
        float yc  = ((float)ii + 0.5f) * (2.0f / (float)HH) - 1.0f;
        float dyv = y - yc;
        float dy2 = dyv * dyv;
        #pragma unroll
        for (int dx = -HXR; dx <= HXR; ++dx) {
            int jj = j0 + dx;
            if (jj < 0 || jj >= WW) continue;
            float xc  = ((float)jj + 0.5f) * (2.0f / (float)WW) - 1.0f;
            float dxv = x - xc;
            float d2  = dxv * dxv + dy2;
            if (!(d2 < R2F)) continue;
            size_t base = (size_t)((b * HH + ii) * WW + jj) * KSLOTS;
            unsigned int key = zbits | (unsigned int)t;
            // safe early reject (invariant (c))
            if (__ldcg(&g_slots[base + KSLOTS - 1]) <= key) continue;
            #pragma unroll
            for (int k = 0; k < KSLOTS; ++k) {
                unsigned int prev = atomicMin(&g_slots[base + k], key);
                if (prev == SENT32) break;     // landed in empty slot
                key = max(key, prev);          // displaced value cascades on
            }
        }
    }
}

// block: 32 pixels x 16 channel-groups (4 ch each) = 512 threads
__global__ void __launch_bounds__(512) gather_kernel(const float* __restrict__ pts,
                                                     float* __restrict__ out) {
    __shared__ float w_s[32][KSLOTS];
    __shared__ int   pid_s[32][KSLOTS];

    int pixBase = blockIdx.x * 32;
    int tid = threadIdx.x;

    // cooperative decode of 32*8 = 256 slots
    if (tid < 256) {
        int px = tid >> 3, k = tid & 7;
        int pix = pixBase + px;
        float wv = 0.0f;
        int   pid = -1;
        unsigned int key = __ldg(&g_slots[(size_t)pix * KSLOTS + k]);
        if (key != SENT32) {
            pid = (int)(key & PIDMASK);
            float x = __ldg(&pts[pid * 3 + 0]);
            float y = __ldg(&pts[pid * 3 + 1]);
            int ij = pix % HWPIX;
            int i = ij / WW, j = ij % WW;
            float xc = ((float)j + 0.5f) * (2.0f / (float)WW) - 1.0f;
            float yc = ((float)i + 0.5f) * (2.0f / (float)HH) - 1.0f;
            float dxv = x - xc, dyv = y - yc;
            float d2 = dxv * dxv + dyv * dyv;
            float dist = d2 / R2F;               // RAD_POW == 2
            dist = fminf(fmaxf(dist, 0.001f), 1.0f);
            wv = 1.0f - sqrtf(dist);             // TAU == 1
        }
        w_s[px][k]  = wv;
        pid_s[px][k] = pid;
    }
    __syncthreads();

    int px  = tid & 31;          // warp spans 32 consecutive pixels
    int cg  = tid >> 5;          // 0..15
    int pix = pixBase + px;

    float4 acc = make_float4(0.f, 0.f, 0.f, 0.f);
    #pragma unroll
    for (int k = 0; k < KSLOTS; ++k) {
        int pid = pid_s[px][k];
        if (pid < 0) break;      // sentinel suffix => valid entries contiguous
        float wv = w_s[px][k];
        const float4 f = *reinterpret_cast<const float4*>(&g_feats[(size_t)pid * CC + cg * 4]);
        acc.x += wv * f.x;
        acc.y += wv * f.y;
        acc.z += wv * f.z;
        acc.w += wv * f.w;
    }

    int b  = pix / HWPIX;
    int ij = pix - b * HWPIX;
    float* o = out + ((size_t)b * CC + cg * 4) * HWPIX + ij;
    o[0 * HWPIX] = acc.x;
    o[1 * HWPIX] = acc.y;
    o[2 * HWPIX] = acc.z;
    o[3 * HWPIX] = acc.w;
}

// ---------------- launch ----------------
extern "C" void kernel_launch(void* const* d_in, const int* in_sizes, int n_in,
                              void* d_out, int out_size) {
    const float* pts = (const float*)d_in[0];   // [B,P,3]
    const float* src = (const float*)d_in[1];   // [B,C,P]
    float* out = (float*)d_out;                 // [B,C,H,W]
    (void)in_sizes; (void)n_in; (void)out_size;

    // 1) reset slots: byte-memset 0xFF == SENT32 (~3.5 us predicted)
    void* slots_ptr = nullptr;
    cudaGetSymbolAddress(&slots_ptr, g_slots);
    cudaMemsetAsync(slots_ptr, 0xFF, (size_t)NPIX * KSLOTS * sizeof(unsigned int), 0);

    // 2) transpose features (~11 us predicted, was 19.6 measured)
    dim3 tb(32, 8);
    dim3 tg(PP / 64, CC / 32, BB);
    transpose_kernel<<<tg, tb>>>(src);

    // 3) scatter into per-pixel top-K z-buffers (u32 atomics)
    scatter_kernel<<<(BB * PP + 255) / 256, 256>>>(pts);

    // 4) gather + composite (output-write-bound)
    gather_kernel<<<NPIX / 32, 512>>>(pts, out);
}